// round 1
// baseline (speedup 1.0000x reference)
#include <cuda_runtime.h>

// YOLOv1 loss, GB300 sm_103a.
// pred:   (16384, 7, 7, 30) f32   d_in[0]
// target: (16384, 7, 7, 30) f32   d_in[1]
// out:    scalar f32
//
// Memory-bound reduction: 192.6 MB read once. Strategy: stage 128 cells/block
// into SMEM with coalesced float4 loads, compute per-cell loss from SMEM,
// hierarchical reduce, one double atomicAdd per block.

#define S_GRID 7
#define N_BATCH 16384
#define N_CELLS (N_BATCH * S_GRID * S_GRID)   // 802816
#define TPB 128
#define FLOATS_PER_CELL 30
#define BLOCK_FLOATS (TPB * FLOATS_PER_CELL)  // 3840
#define BLOCK_VEC4 (BLOCK_FLOATS / 4)         // 960

__device__ double g_acc;

__global__ void yolo_zero_kernel() {
    g_acc = 0.0;
}

__global__ void __launch_bounds__(TPB) yolo_loss_kernel(
    const float* __restrict__ pred,
    const float* __restrict__ targ)
{
    __shared__ float sp[BLOCK_FLOATS];
    __shared__ float st[BLOCK_FLOATS];
    __shared__ float warpsum[TPB / 32];

    const int tid = threadIdx.x;
    const long long cell0 = (long long)blockIdx.x * TPB;

    // ---- Coalesced float4 staging (block region is contiguous & 16B-aligned:
    //      byte offset = blockIdx * 128*30*4 = blockIdx * 15360) ----
    const float4* __restrict__ gp = (const float4*)(pred + cell0 * FLOATS_PER_CELL);
    const float4* __restrict__ gt = (const float4*)(targ + cell0 * FLOATS_PER_CELL);
    float4* s4p = (float4*)sp;
    float4* s4t = (float4*)st;

#pragma unroll
    for (int i = 0; i < BLOCK_VEC4 / TPB; i++) {      // 960/128 = 7.5 -> 7 full
        int idx = tid + i * TPB;
        s4p[idx] = gp[idx];
        s4t[idx] = gt[idx];
    }
    {   // remainder (960 % 128 = 64)
        int idx = tid + (BLOCK_VEC4 / TPB) * TPB;
        if (idx < BLOCK_VEC4) {
            s4p[idx] = gp[idx];
            s4t[idx] = gt[idx];
        }
    }
    __syncthreads();

    // ---- Per-cell loss ----
    const float* p = sp + tid * FLOATS_PER_CELL;
    const float* t = st + tid * FLOATS_PER_CELL;

    const float coo = (t[4] > 0.0f) ? 1.0f : 0.0f;
    const float noo = 1.0f - coo;

    // no-object confidence loss (weight 0.5)
    float d4 = p[4] - t[4];
    float d9 = p[9] - t[9];
    float loss = 0.5f * noo * (d4 * d4 + d9 * d9);

    // class loss: channels 10..29
    float cls = 0.0f;
#pragma unroll
    for (int k = 10; k < 30; k++) {
        float d = p[k] - t[k];
        cls += d * d;
    }
    loss += coo * cls;

    // ---- Box responsibility via (degenerate) IoU, matching the reference
    //      exactly: inter = 1 iff (rb-lt)<0 in BOTH dims, else 0. ----
    const float t_ltx = t[0] - 0.5f * t[2];
    const float t_lty = t[1] - 0.5f * t[3];
    const float t_rbx = t[0] + 0.5f * t[2];
    const float t_rby = t[1] + 0.5f * t[3];
    const float area2 = (t_rbx - t_ltx) * (t_rby - t_lty);

    float iou[2];
#pragma unroll
    for (int b = 0; b < 2; b++) {
        const float* pb = p + b * 5;
        float p_ltx = pb[0] - 0.5f * pb[2];
        float p_lty = pb[1] - 0.5f * pb[3];
        float p_rbx = pb[0] + 0.5f * pb[2];
        float p_rby = pb[1] + 0.5f * pb[3];
        float ltx = fmaxf(p_ltx, t_ltx);
        float lty = fmaxf(p_lty, t_lty);
        float rbx = fminf(p_rbx, t_rbx);
        float rby = fminf(p_rby, t_rby);
        float wh0 = (rbx - ltx < 0.0f) ? 1.0f : 0.0f;
        float wh1 = (rby - lty < 0.0f) ? 1.0f : 0.0f;
        float inter = wh0 * wh1;
        float area1 = (p_rbx - p_ltx) * (p_rby - p_lty);
        iou[b] = inter / (area1 + area2 - inter);
    }
    // jnp.argmax: first index on ties -> idx = 1 only if strictly greater
    const int idx = (iou[1] > iou[0]) ? 1 : 0;
    const float* rp = p + idx * 5;
    const float* rt = t + idx * 5;

    // containing-object confidence loss
    float dc = rp[4] - rt[4];
    loss += coo * dc * dc;

    // localization loss (weight 5): xy + sqrt(wh)
    float dx = rp[0] - rt[0];
    float dy = rp[1] - rt[1];
    // where(safe, v, 1.0) sqrt guard, exactly as reference
    float wp2 = (coo > 0.0f) ? rp[2] : 1.0f;
    float wp3 = (coo > 0.0f) ? rp[3] : 1.0f;
    float wt2 = (coo > 0.0f) ? rt[2] : 1.0f;
    float wt3 = (coo > 0.0f) ? rt[3] : 1.0f;
    float dw = sqrtf(wp2) - sqrtf(wt2);
    float dh = sqrtf(wp3) - sqrtf(wt3);
    loss += 5.0f * coo * (dx * dx + dy * dy + dw * dw + dh * dh);

    // ---- Block reduction ----
#pragma unroll
    for (int o = 16; o > 0; o >>= 1)
        loss += __shfl_xor_sync(0xFFFFFFFFu, loss, o);
    if ((tid & 31) == 0)
        warpsum[tid >> 5] = loss;
    __syncthreads();
    if (tid == 0) {
        float s = 0.0f;
#pragma unroll
        for (int w = 0; w < TPB / 32; w++)
            s += warpsum[w];
        atomicAdd(&g_acc, (double)s * (1.0 / (double)N_BATCH));
    }
}

__global__ void yolo_write_kernel(float* __restrict__ out) {
    out[0] = (float)g_acc;
}

extern "C" void kernel_launch(void* const* d_in, const int* in_sizes, int n_in,
                              void* d_out, int out_size) {
    (void)in_sizes; (void)n_in; (void)out_size;
    const float* pred = (const float*)d_in[0];
    const float* targ = (const float*)d_in[1];
    float* out = (float*)d_out;

    yolo_zero_kernel<<<1, 1>>>();
    yolo_loss_kernel<<<N_CELLS / TPB, TPB>>>(pred, targ);  // 6272 blocks
    yolo_write_kernel<<<1, 1>>>(out);
}